// round 1
// baseline (speedup 1.0000x reference)
#include <cuda_runtime.h>
#include <math.h>

// Problem constants
#define B_  2
#define S_  2048
#define D_  1024
#define H_  16
#define DK_ 64
#define M_  (B_ * S_)              // 4096
#define OUT_ELEMS (B_ * S_ * D_)   // 4194304  (output part of d_out)

// Scratch (device globals; no allocations allowed)
__device__ float g_qh[B_ * H_ * S_ * DK_];   // [b][h][s][d]
__device__ float g_kh[B_ * H_ * S_ * DK_];
__device__ float g_vh[B_ * H_ * S_ * DK_];
__device__ float g_ctx[M_ * D_];             // [b*S+s][h*64+d]

// ---------------------------------------------------------------------------
// Classic 128x128x8 SGEMM with float4, optional bias, optional head-permute
// output. A: [M,K] row-major. B: [K,N] row-major. 256 threads, 8x8 per thread.
// ---------------------------------------------------------------------------
template <bool PERMUTE>
__global__ __launch_bounds__(256) void sgemm_bias_kernel(
    const float* __restrict__ A, const float* __restrict__ Bm,
    const float* __restrict__ bias, float* __restrict__ C,
    int M, int N, int K)
{
    const int BM = 128, BN = 128, BK = 8;
    __shared__ float As[BK][BM];
    __shared__ float Bs[BK][BN];

    const int t = threadIdx.x;
    const int block_row = blockIdx.y * BM;
    const int block_col = blockIdx.x * BN;

    // A-tile load coords: 128 rows x 8 cols -> 256 float4 (one per thread)
    const int a_row  = t >> 1;            // 0..127
    const int a_col4 = (t & 1) << 2;      // 0 or 4
    // B-tile load coords: 8 rows x 128 cols -> 256 float4
    const int b_row  = t >> 5;            // 0..7
    const int b_col4 = (t & 31) << 2;     // 0..124

    const int tr = (t >> 4) << 3;         // 0..120 step 8
    const int tc = (t & 15) << 3;         // 0..120 step 8

    float acc[8][8];
#pragma unroll
    for (int i = 0; i < 8; i++)
#pragma unroll
        for (int j = 0; j < 8; j++) acc[i][j] = 0.f;

    const float* Aptr = A + (size_t)(block_row + a_row) * K + a_col4;
    const float* Bptr = Bm + (size_t)b_row * N + block_col + b_col4;

    for (int k0 = 0; k0 < K; k0 += BK) {
        float4 av = *(const float4*)(Aptr + k0);
        float4 bv = *(const float4*)(Bptr + (size_t)k0 * N);
        As[a_col4 + 0][a_row] = av.x;
        As[a_col4 + 1][a_row] = av.y;
        As[a_col4 + 2][a_row] = av.z;
        As[a_col4 + 3][a_row] = av.w;
        *(float4*)&Bs[b_row][b_col4] = bv;
        __syncthreads();

#pragma unroll
        for (int kk = 0; kk < BK; kk++) {
            float ra[8], rb[8];
            *(float4*)&ra[0] = *(const float4*)&As[kk][tr];
            *(float4*)&ra[4] = *(const float4*)&As[kk][tr + 4];
            *(float4*)&rb[0] = *(const float4*)&Bs[kk][tc];
            *(float4*)&rb[4] = *(const float4*)&Bs[kk][tc + 4];
#pragma unroll
            for (int i = 0; i < 8; i++)
#pragma unroll
                for (int j = 0; j < 8; j++) acc[i][j] = fmaf(ra[i], rb[j], acc[i][j]);
        }
        __syncthreads();
    }

    // Epilogue
#pragma unroll
    for (int i = 0; i < 8; i++) {
        const int row = block_row + tr + i;
#pragma unroll
        for (int j = 0; j < 8; j++) {
            const int col = block_col + tc + j;
            float v = acc[i][j] + bias[col];
            if (PERMUTE) {
                // [m, n] -> qh[b][h][s][d]
                const int b = row >> 11;        // /S_
                const int s = row & (S_ - 1);
                const int h = col >> 6;         // /DK_
                const int d = col & (DK_ - 1);
                g_qh[0]; // (keep template honest; output via C)
                C[(((size_t)(b * H_ + h) * S_) + s) * DK_ + d] = v;
            } else {
                C[(size_t)row * N + col] = v;
            }
        }
    }
}

// ---------------------------------------------------------------------------
// Scores: per (b,h): attn_raw[s][t] = (Q[s,:].K[t,:]) / 8, 64x64 tile/block.
// Q,K stored [bh][s][64]. Output into d_out attn region (row stride S_).
// ---------------------------------------------------------------------------
__global__ __launch_bounds__(256) void scores_kernel(
    const float* __restrict__ qh, const float* __restrict__ kh,
    float* __restrict__ attn)
{
    __shared__ float Qs[64][65];   // [d][s]
    __shared__ float Ks[64][65];   // [d][t]
    const int bh = blockIdx.z;
    const float* Q = qh + ((size_t)bh * S_ + blockIdx.y * 64) * DK_;
    const float* Kp = kh + ((size_t)bh * S_ + blockIdx.x * 64) * DK_;
    const int t = threadIdx.x;

#pragma unroll
    for (int i = 0; i < 4; i++) {
        const int idx = t + i * 256;          // 0..1023
        const int row = idx >> 4;             // 0..63
        const int c4  = (idx & 15) << 2;      // 0..60
        float4 qv = *(const float4*)(Q + row * 64 + c4);
        Qs[c4 + 0][row] = qv.x; Qs[c4 + 1][row] = qv.y;
        Qs[c4 + 2][row] = qv.z; Qs[c4 + 3][row] = qv.w;
        float4 kv = *(const float4*)(Kp + row * 64 + c4);
        Ks[c4 + 0][row] = kv.x; Ks[c4 + 1][row] = kv.y;
        Ks[c4 + 2][row] = kv.z; Ks[c4 + 3][row] = kv.w;
    }
    __syncthreads();

    const int tr = (t >> 4) << 2;   // 4 rows
    const int tc = (t & 15) << 2;   // 4 cols
    float acc[4][4];
#pragma unroll
    for (int i = 0; i < 4; i++)
#pragma unroll
        for (int j = 0; j < 4; j++) acc[i][j] = 0.f;

#pragma unroll 8
    for (int d = 0; d < 64; d++) {
        float a0 = Qs[d][tr], a1 = Qs[d][tr + 1], a2 = Qs[d][tr + 2], a3 = Qs[d][tr + 3];
        float b0 = Ks[d][tc], b1 = Ks[d][tc + 1], b2 = Ks[d][tc + 2], b3 = Ks[d][tc + 3];
        acc[0][0] = fmaf(a0, b0, acc[0][0]); acc[0][1] = fmaf(a0, b1, acc[0][1]);
        acc[0][2] = fmaf(a0, b2, acc[0][2]); acc[0][3] = fmaf(a0, b3, acc[0][3]);
        acc[1][0] = fmaf(a1, b0, acc[1][0]); acc[1][1] = fmaf(a1, b1, acc[1][1]);
        acc[1][2] = fmaf(a1, b2, acc[1][2]); acc[1][3] = fmaf(a1, b3, acc[1][3]);
        acc[2][0] = fmaf(a2, b0, acc[2][0]); acc[2][1] = fmaf(a2, b1, acc[2][1]);
        acc[2][2] = fmaf(a2, b2, acc[2][2]); acc[2][3] = fmaf(a2, b3, acc[2][3]);
        acc[3][0] = fmaf(a3, b0, acc[3][0]); acc[3][1] = fmaf(a3, b1, acc[3][1]);
        acc[3][2] = fmaf(a3, b2, acc[3][2]); acc[3][3] = fmaf(a3, b3, acc[3][3]);
    }

    const float scale = 0.125f;   // 1/sqrt(64)
#pragma unroll
    for (int i = 0; i < 4; i++) {
        const size_t row = (size_t)bh * S_ + blockIdx.y * 64 + tr + i;
        float4 o;
        o.x = acc[i][0] * scale; o.y = acc[i][1] * scale;
        o.z = acc[i][2] * scale; o.w = acc[i][3] * scale;
        *(float4*)(attn + row * S_ + blockIdx.x * 64 + tc) = o;
    }
}

// ---------------------------------------------------------------------------
// Row softmax in-place on attn (row length S_=2048). One block per row.
// ---------------------------------------------------------------------------
__global__ __launch_bounds__(256) void softmax_kernel(float* __restrict__ attn)
{
    const size_t row = blockIdx.x;
    float* p = attn + row * S_;
    const int t = threadIdx.x;

    float v[8];
    float mx = -1e30f;
#pragma unroll
    for (int i = 0; i < 8; i++) { v[i] = p[t + 256 * i]; mx = fmaxf(mx, v[i]); }
#pragma unroll
    for (int o = 16; o; o >>= 1) mx = fmaxf(mx, __shfl_xor_sync(0xffffffffu, mx, o));

    __shared__ float red[8];
    if ((t & 31) == 0) red[t >> 5] = mx;
    __syncthreads();
    mx = red[0];
#pragma unroll
    for (int i = 1; i < 8; i++) mx = fmaxf(mx, red[i]);
    __syncthreads();

    float sum = 0.f;
#pragma unroll
    for (int i = 0; i < 8; i++) { v[i] = expf(v[i] - mx); sum += v[i]; }
#pragma unroll
    for (int o = 16; o; o >>= 1) sum += __shfl_xor_sync(0xffffffffu, sum, o);
    if ((t & 31) == 0) red[t >> 5] = sum;
    __syncthreads();
    sum = 0.f;
#pragma unroll
    for (int i = 0; i < 8; i++) sum += red[i];

    const float inv = 1.0f / sum;
#pragma unroll
    for (int i = 0; i < 8; i++) p[t + 256 * i] = v[i] * inv;
}

// ---------------------------------------------------------------------------
// ctx: per (b,h): C[s][d] = sum_t attn[s][t] * V[t][d]; 64x64 tile per block,
// K-loop over 2048 in 64-chunks. Writes ctx to [b*S+s][h*64+d] layout.
// ---------------------------------------------------------------------------
__global__ __launch_bounds__(256) void ctx_kernel(
    const float* __restrict__ attn, const float* __restrict__ vh,
    float* __restrict__ ctx)
{
    __shared__ float As[64][65];   // [t][s]  (attn tile, transposed)
    __shared__ float Vs[64][65];   // [t][d]
    const int bh = blockIdx.y;
    const int s0 = blockIdx.x * 64;
    const int t = threadIdx.x;

    const float* Abase = attn + ((size_t)bh * S_ + s0) * S_;
    const float* Vbase = vh + (size_t)bh * S_ * DK_;

    const int tr = (t >> 4) << 2;
    const int tc = (t & 15) << 2;
    float acc[4][4];
#pragma unroll
    for (int i = 0; i < 4; i++)
#pragma unroll
        for (int j = 0; j < 4; j++) acc[i][j] = 0.f;

    for (int k0 = 0; k0 < S_; k0 += 64) {
#pragma unroll
        for (int i = 0; i < 4; i++) {
            const int idx = t + i * 256;
            const int row = idx >> 4;         // 0..63
            const int c4  = (idx & 15) << 2;  // 0..60
            float4 av = *(const float4*)(Abase + (size_t)row * S_ + k0 + c4);
            As[c4 + 0][row] = av.x; As[c4 + 1][row] = av.y;
            As[c4 + 2][row] = av.z; As[c4 + 3][row] = av.w;
            float4 vv = *(const float4*)(Vbase + (size_t)(k0 + row) * DK_ + c4);
            Vs[row][c4 + 0] = vv.x; Vs[row][c4 + 1] = vv.y;
            Vs[row][c4 + 2] = vv.z; Vs[row][c4 + 3] = vv.w;
        }
        __syncthreads();

#pragma unroll 8
        for (int k = 0; k < 64; k++) {
            float a0 = As[k][tr], a1 = As[k][tr + 1], a2 = As[k][tr + 2], a3 = As[k][tr + 3];
            float b0 = Vs[k][tc], b1 = Vs[k][tc + 1], b2 = Vs[k][tc + 2], b3 = Vs[k][tc + 3];
            acc[0][0] = fmaf(a0, b0, acc[0][0]); acc[0][1] = fmaf(a0, b1, acc[0][1]);
            acc[0][2] = fmaf(a0, b2, acc[0][2]); acc[0][3] = fmaf(a0, b3, acc[0][3]);
            acc[1][0] = fmaf(a1, b0, acc[1][0]); acc[1][1] = fmaf(a1, b1, acc[1][1]);
            acc[1][2] = fmaf(a1, b2, acc[1][2]); acc[1][3] = fmaf(a1, b3, acc[1][3]);
            acc[2][0] = fmaf(a2, b0, acc[2][0]); acc[2][1] = fmaf(a2, b1, acc[2][1]);
            acc[2][2] = fmaf(a2, b2, acc[2][2]); acc[2][3] = fmaf(a2, b3, acc[2][3]);
            acc[3][0] = fmaf(a3, b0, acc[3][0]); acc[3][1] = fmaf(a3, b1, acc[3][1]);
            acc[3][2] = fmaf(a3, b2, acc[3][2]); acc[3][3] = fmaf(a3, b3, acc[3][3]);
        }
        __syncthreads();
    }

    const int b = bh >> 4;
    const int h = bh & 15;
#pragma unroll
    for (int i = 0; i < 4; i++) {
        const size_t m = (size_t)b * S_ + s0 + tr + i;
        float4 o;
        o.x = acc[i][0]; o.y = acc[i][1]; o.z = acc[i][2]; o.w = acc[i][3];
        *(float4*)(ctx + m * D_ + h * DK_ + tc) = o;
    }
}

// ---------------------------------------------------------------------------
extern "C" void kernel_launch(void* const* d_in, const int* in_sizes, int n_in,
                              void* d_out, int out_size)
{
    const float* q  = (const float*)d_in[0];
    const float* k  = (const float*)d_in[1];
    const float* v  = (const float*)d_in[2];
    const float* wq = (const float*)d_in[3];
    const float* bq = (const float*)d_in[4];
    const float* wk = (const float*)d_in[5];
    const float* bk = (const float*)d_in[6];
    const float* wv = (const float*)d_in[7];
    const float* bv = (const float*)d_in[8];
    const float* wo = (const float*)d_in[9];
    const float* bo = (const float*)d_in[10];

    float* out  = (float*)d_out;            // [B,S,D]
    float* attn = out + OUT_ELEMS;          // [B,H,S,S]

    float *qh, *kh, *vh, *ctx;
    cudaGetSymbolAddress((void**)&qh, g_qh);
    cudaGetSymbolAddress((void**)&kh, g_kh);
    cudaGetSymbolAddress((void**)&vh, g_vh);
    cudaGetSymbolAddress((void**)&ctx, g_ctx);

    dim3 gProj(D_ / 128, M_ / 128);         // (8, 32)

    sgemm_bias_kernel<true><<<gProj, 256>>>(q, wq, bq, qh, M_, D_, D_);
    sgemm_bias_kernel<true><<<gProj, 256>>>(k, wk, bk, kh, M_, D_, D_);
    sgemm_bias_kernel<true><<<gProj, 256>>>(v, wv, bv, vh, M_, D_, D_);

    scores_kernel<<<dim3(S_ / 64, S_ / 64, B_ * H_), 256>>>(qh, kh, attn);
    softmax_kernel<<<B_ * H_ * S_, 256>>>(attn);
    ctx_kernel<<<dim3(S_ / 64, B_ * H_), 256>>>(attn, vh, ctx);

    sgemm_bias_kernel<false><<<gProj, 256>>>(ctx, wo, bo, out, M_, D_, D_);
}

// round 3
// speedup vs baseline: 1.5246x; 1.5246x over previous
#include <cuda_runtime.h>
#include <cuda_bf16.h>
#include <cstdint>
#include <math.h>

// Problem constants
#define B_  2
#define S_  2048
#define D_  1024
#define H_  16
#define DK_ 64
#define M_  (B_ * S_)              // 4096
#define OUT_ELEMS (B_ * S_ * D_)   // 4194304

// ---------------------------------------------------------------------------
// Helpers
// ---------------------------------------------------------------------------
__device__ __forceinline__ uint32_t smem_u32(const void* p) {
    uint32_t a;
    asm("{ .reg .u64 t; cvta.to.shared.u64 t, %1; cvt.u32.u64 %0, t; }" : "=r"(a) : "l"(p));
    return a;
}
#define SWZ128(off) ((off) ^ (((off) >> 3) & 0x70))

__device__ __forceinline__ void cp_async16(uint32_t dst, const void* src) {
    asm volatile("cp.async.cg.shared.global [%0], [%1], 16;" :: "r"(dst), "l"(src));
}
#define CP_COMMIT() asm volatile("cp.async.commit_group;" ::: "memory")
#define CP_WAIT(n)  asm volatile("cp.async.wait_group %0;" :: "n"(n) : "memory")

__device__ __forceinline__ void ldsm4(uint32_t* r, uint32_t addr) {
    asm volatile("ldmatrix.sync.aligned.m8n8.x4.shared.b16 {%0,%1,%2,%3}, [%4];"
                 : "=r"(r[0]), "=r"(r[1]), "=r"(r[2]), "=r"(r[3]) : "r"(addr));
}

__device__ __forceinline__ void mma_bf16(float* c, const uint32_t* a, uint32_t b0, uint32_t b1) {
    asm volatile(
        "mma.sync.aligned.m16n8k16.row.col.f32.bf16.bf16.f32 "
        "{%0,%1,%2,%3}, {%4,%5,%6,%7}, {%8,%9}, {%0,%1,%2,%3};"
        : "+f"(c[0]), "+f"(c[1]), "+f"(c[2]), "+f"(c[3])
        : "r"(a[0]), "r"(a[1]), "r"(a[2]), "r"(a[3]), "r"(b0), "r"(b1));
}

// ---------------------------------------------------------------------------
// Scratch (device globals)
// ---------------------------------------------------------------------------
__device__ float g_qh[B_ * H_ * S_ * DK_];
__device__ float g_kh[B_ * H_ * S_ * DK_];
__device__ float g_vh[B_ * H_ * S_ * DK_];
__device__ float g_ctx[M_ * D_];
__device__ __nv_bfloat16 g_xcat[M_ * 3 * D_];          // activations [4096, 3072]
__device__ __nv_bfloat16 g_wcat[D_ * 3 * D_];          // weight^T    [1024, 3072]
__device__ __nv_bfloat16 g_qcat[B_ * H_ * S_ * 3 * DK_]; // [bh*s, 192]
__device__ __nv_bfloat16 g_kcat[B_ * H_ * S_ * 3 * DK_];

// ---------------------------------------------------------------------------
// Split fp32 -> bf16 [hi | (lo or hi) | (hi or lo)] concat along K.
// STYLE 0 (A-side): [hi | lo | hi].  STYLE 1 (B-side): [hi | hi | lo].
// ---------------------------------------------------------------------------
template<int KIN, int STYLE>
__global__ __launch_bounds__(256) void split_cat_kernel(
    const float* __restrict__ x, __nv_bfloat16* __restrict__ out)
{
    const int i2 = blockIdx.x * 256 + threadIdx.x;
    const int r  = i2 / (KIN / 2);
    const int kp = (i2 - r * (KIN / 2)) * 2;
    float2 f = *(const float2*)(x + (size_t)r * KIN + kp);
    __nv_bfloat16 h0 = __float2bfloat16(f.x);
    __nv_bfloat16 h1 = __float2bfloat16(f.y);
    __nv_bfloat16 l0 = __float2bfloat16(f.x - __bfloat162float(h0));
    __nv_bfloat16 l1 = __float2bfloat16(f.y - __bfloat162float(h1));
    __nv_bfloat162 hv; hv.x = h0; hv.y = h1;
    __nv_bfloat162 lv; lv.x = l0; lv.y = l1;
    __nv_bfloat16* base = out + (size_t)r * 3 * KIN;
    *(__nv_bfloat162*)(base + kp) = hv;
    if (STYLE == 0) {
        *(__nv_bfloat162*)(base + KIN + kp)     = lv;
        *(__nv_bfloat162*)(base + 2 * KIN + kp) = hv;
    } else {
        *(__nv_bfloat162*)(base + KIN + kp)     = hv;
        *(__nv_bfloat162*)(base + 2 * KIN + kp) = lv;
    }
}

// Transpose [K=1024, N=1024] fp32 -> B' [N, 3072] bf16 = [Bh | Bh | Bl]
__global__ __launch_bounds__(256) void transpose_split_cat_kernel(
    const float* __restrict__ w, __nv_bfloat16* __restrict__ out)
{
    __shared__ float tile[32][33];
    const int k0 = blockIdx.y * 32;
    const int n0 = blockIdx.x * 32;
    const int tx = threadIdx.x & 31;
    const int ty = threadIdx.x >> 5;   // 0..7
#pragma unroll
    for (int i = 0; i < 4; i++)
        tile[ty + i * 8][tx] = w[(size_t)(k0 + ty + i * 8) * D_ + n0 + tx];
    __syncthreads();
#pragma unroll
    for (int i = 0; i < 4; i++) {
        float f = tile[tx][ty + i * 8];        // w[k0+tx][n0+ty+i*8]
        __nv_bfloat16 h = __float2bfloat16(f);
        __nv_bfloat16 l = __float2bfloat16(f - __bfloat162float(h));
        const size_t n = n0 + ty + i * 8;
        const size_t k = k0 + tx;
        out[n * 3072 + k]        = h;
        out[n * 3072 + 1024 + k] = h;
        out[n * 3072 + 2048 + k] = l;
    }
}

// ---------------------------------------------------------------------------
// bf16 mma.sync GEMM: C[m][n] = scale * sum_k A[m][k]*B[n][k] (+ bias[n])
// A: [*, lda] bf16 K-major.  B: [*, ldb] bf16 K-major.  Kp multiple of 64.
// Block 128x128, 8 warps (64x32 warp tiles), BK=64, 3-stage cp.async.
// permute=1: C index mapped [m,n] -> [b][h][s][d] head-split layout.
// ---------------------------------------------------------------------------
#define GEMM_STAGES 3
#define GEMM_SMEM_SZ (GEMM_STAGES * 32768)

__global__ __launch_bounds__(256, 1) void gemm_mma_kernel(
    const __nv_bfloat16* __restrict__ A, int lda, long long strideA,
    const __nv_bfloat16* __restrict__ B, int ldb, long long strideB,
    float* __restrict__ C, int ldc, long long strideC,
    const float* __restrict__ bias, float scale, int Kp, int permute)
{
    extern __shared__ char smem[];
    const uint32_t sbase = smem_u32(smem);
    const int t = threadIdx.x;
    const int lane = t & 31;
    const int wid = t >> 5;
    const int wm = (wid >> 2) * 64;
    const int wn = (wid & 3) * 32;
    const int m0 = blockIdx.y * 128;
    const int n0 = blockIdx.x * 128;
    const int z = blockIdx.z;

    const char* Ab = (const char*)(A + (size_t)z * strideA + (size_t)m0 * lda);
    const char* Bb = (const char*)(B + (size_t)z * strideB + (size_t)n0 * ldb);
    float* Cb = C + (size_t)z * strideC;

    const int ktiles = Kp >> 6;

    // per-thread cp.async coords: 4 iterations, each loads one 16B chunk of A
    // and one of B. id in [0,1024): row = id>>3 (0..127), cb = (id&7)*16 bytes.
    auto load_stage = [&](int kt, int s) {
        const uint32_t sa = sbase + (uint32_t)s * 32768u;
#pragma unroll
        for (int i = 0; i < 4; i++) {
            const int id = t + i * 256;
            const int row = id >> 3;
            const int cb = (id & 7) << 4;
            const uint32_t sw = SWZ128((uint32_t)(row * 128 + cb));
            const size_t goff = (size_t)row * lda * 2 + (size_t)kt * 128 + cb;
            const size_t goffB = (size_t)row * ldb * 2 + (size_t)kt * 128 + cb;
            cp_async16(sa + sw, Ab + goff);
            cp_async16(sa + 16384u + sw, Bb + goffB);
        }
        CP_COMMIT();
    };

    float acc[4][4][4];
#pragma unroll
    for (int i = 0; i < 4; i++)
#pragma unroll
        for (int j = 0; j < 4; j++)
#pragma unroll
            for (int k = 0; k < 4; k++) acc[i][j][k] = 0.f;

    load_stage(0, 0);
    if (ktiles > 1) load_stage(1, 1);

    int st = 0;
    for (int kt = 0; kt < ktiles; kt++) {
        if (kt + 2 < ktiles) {
            int s2 = st + 2; if (s2 >= GEMM_STAGES) s2 -= GEMM_STAGES;
            load_stage(kt + 2, s2);
            CP_WAIT(2);
        } else {
            CP_WAIT(0);
        }
        __syncthreads();

        const uint32_t sa = sbase + (uint32_t)st * 32768u;
        const uint32_t sb = sa + 16384u;

#pragma unroll
        for (int ks = 0; ks < 4; ks++) {
            uint32_t af[4][4];
#pragma unroll
            for (int im = 0; im < 4; im++) {
                const int row = wm + im * 16 + (lane & 15);
                const int byt = ks * 32 + ((lane >> 4) << 4);
                ldsm4(af[im], sa + SWZ128((uint32_t)(row * 128 + byt)));
            }
            uint32_t bf[2][4];
#pragma unroll
            for (int j = 0; j < 2; j++) {
                const int nrow = wn + j * 16 + (lane & 7) + ((lane & 16) ? 8 : 0);
                const int byt = ks * 32 + ((lane & 8) ? 16 : 0);
                ldsm4(bf[j], sb + SWZ128((uint32_t)(nrow * 128 + byt)));
            }
#pragma unroll
            for (int im = 0; im < 4; im++)
#pragma unroll
                for (int in = 0; in < 4; in++) {
                    const uint32_t* bb = &bf[in >> 1][(in & 1) * 2];
                    mma_bf16(acc[im][in], af[im], bb[0], bb[1]);
                }
        }
        __syncthreads();
        st++; if (st >= GEMM_STAGES) st = 0;
    }

    // Epilogue
#pragma unroll
    for (int im = 0; im < 4; im++) {
        const int r0 = m0 + wm + im * 16 + (lane >> 2);
#pragma unroll
        for (int in = 0; in < 4; in++) {
            const int col = n0 + wn + in * 8 + (lane & 3) * 2;
            float2 v0, v1;
            v0.x = acc[im][in][0] * scale;
            v0.y = acc[im][in][1] * scale;
            v1.x = acc[im][in][2] * scale;
            v1.y = acc[im][in][3] * scale;
            if (bias) {
                const float b0 = __ldg(bias + col), b1 = __ldg(bias + col + 1);
                v0.x += b0; v0.y += b1;
                v1.x += b0; v1.y += b1;
            }
            if (permute) {
                const int h = col >> 6, d0 = col & 63;
                const int bb0 = r0 >> 11, s0 = r0 & (S_ - 1);
                const int r1 = r0 + 8;
                const int bb1 = r1 >> 11, s1 = r1 & (S_ - 1);
                *(float2*)(Cb + (((size_t)(bb0 * H_ + h) * S_ + s0) * DK_ + d0)) = v0;
                *(float2*)(Cb + (((size_t)(bb1 * H_ + h) * S_ + s1) * DK_ + d0)) = v1;
            } else {
                *(float2*)(Cb + (size_t)r0 * ldc + col) = v0;
                *(float2*)(Cb + (size_t)(r0 + 8) * ldc + col) = v1;
            }
        }
    }
}

// ---------------------------------------------------------------------------
// Row softmax in-place (row length 2048), one block/row
// ---------------------------------------------------------------------------
__global__ __launch_bounds__(256) void softmax_kernel(float* __restrict__ attn)
{
    const size_t row = blockIdx.x;
    float* p = attn + row * S_;
    const int t = threadIdx.x;

    float v[8];
    float mx = -1e30f;
#pragma unroll
    for (int i = 0; i < 8; i++) { v[i] = p[t + 256 * i]; mx = fmaxf(mx, v[i]); }
#pragma unroll
    for (int o = 16; o; o >>= 1) mx = fmaxf(mx, __shfl_xor_sync(0xffffffffu, mx, o));

    __shared__ float red[8];
    if ((t & 31) == 0) red[t >> 5] = mx;
    __syncthreads();
    mx = red[0];
#pragma unroll
    for (int i = 1; i < 8; i++) mx = fmaxf(mx, red[i]);
    __syncthreads();

    float sum = 0.f;
#pragma unroll
    for (int i = 0; i < 8; i++) { v[i] = expf(v[i] - mx); sum += v[i]; }
#pragma unroll
    for (int o = 16; o; o >>= 1) sum += __shfl_xor_sync(0xffffffffu, sum, o);
    if ((t & 31) == 0) red[t >> 5] = sum;
    __syncthreads();
    sum = 0.f;
#pragma unroll
    for (int i = 0; i < 8; i++) sum += red[i];

    const float inv = 1.0f / sum;
#pragma unroll
    for (int i = 0; i < 8; i++) p[t + 256 * i] = v[i] * inv;
}

// ---------------------------------------------------------------------------
// ctx: 128x64 tile per block (128 threads, 8x8/thread), K loop over 2048
// ---------------------------------------------------------------------------
__global__ __launch_bounds__(128) void ctx128_kernel(
    const float* __restrict__ attn, const float* __restrict__ vh, float* __restrict__ ctx)
{
    extern __shared__ float sm[];
    float* As = sm;              // [64][128]  As[k][s]
    float* Vs = sm + 64 * 128;   // [64][64]   Vs[k][d]

    const int bh = blockIdx.y;
    const int s0 = blockIdx.x * 128;
    const int t = threadIdx.x;

    const float* Abase = attn + ((size_t)bh * S_ + s0) * S_;
    const float* Vbase = vh + (size_t)bh * S_ * DK_;

    const int tr = (t >> 3) << 3;
    const int tc = (t & 7) << 3;
    float acc[8][8];
#pragma unroll
    for (int i = 0; i < 8; i++)
#pragma unroll
        for (int j = 0; j < 8; j++) acc[i][j] = 0.f;

    for (int k0 = 0; k0 < S_; k0 += 64) {
#pragma unroll
        for (int i = 0; i < 16; i++) {
            const int idx = t + i * 128;
            const int row = idx >> 4;
            const int c4 = (idx & 15) << 2;
            float4 av = *(const float4*)(Abase + (size_t)row * S_ + k0 + c4);
            As[(c4 + 0) * 128 + row] = av.x; As[(c4 + 1) * 128 + row] = av.y;
            As[(c4 + 2) * 128 + row] = av.z; As[(c4 + 3) * 128 + row] = av.w;
        }
#pragma unroll
        for (int i = 0; i < 8; i++) {
            const int idx = t + i * 128;
            const int row = idx >> 4;
            const int c4 = (idx & 15) << 2;
            float4 vv = *(const float4*)(Vbase + (size_t)(k0 + row) * DK_ + c4);
            *(float4*)&Vs[row * 64 + c4] = vv;
        }
        __syncthreads();

#pragma unroll 4
        for (int k = 0; k < 64; k++) {
            float ra[8], rb[8];
            *(float4*)&ra[0] = *(const float4*)&As[k * 128 + tr];
            *(float4*)&ra[4] = *(const float4*)&As[k * 128 + tr + 4];
            *(float4*)&rb[0] = *(const float4*)&Vs[k * 64 + tc];
            *(float4*)&rb[4] = *(const float4*)&Vs[k * 64 + tc + 4];
#pragma unroll
            for (int i = 0; i < 8; i++)
#pragma unroll
                for (int j = 0; j < 8; j++) acc[i][j] = fmaf(ra[i], rb[j], acc[i][j]);
        }
        __syncthreads();
    }

    const int b = bh >> 4, h = bh & 15;
#pragma unroll
    for (int i = 0; i < 8; i++) {
        const size_t m = (size_t)b * S_ + s0 + tr + i;
        float* p = ctx + m * D_ + h * DK_ + tc;
        float4 o0, o1;
        o0.x = acc[i][0]; o0.y = acc[i][1]; o0.z = acc[i][2]; o0.w = acc[i][3];
        o1.x = acc[i][4]; o1.y = acc[i][5]; o1.z = acc[i][6]; o1.w = acc[i][7];
        *(float4*)p = o0;
        *(float4*)(p + 4) = o1;
    }
}

// ---------------------------------------------------------------------------
extern "C" void kernel_launch(void* const* d_in, const int* in_sizes, int n_in,
                              void* d_out, int out_size)
{
    const float* q  = (const float*)d_in[0];
    const float* k  = (const float*)d_in[1];
    const float* v  = (const float*)d_in[2];
    const float* wq = (const float*)d_in[3];
    const float* bq = (const float*)d_in[4];
    const float* wk = (const float*)d_in[5];
    const float* bk = (const float*)d_in[6];
    const float* wv = (const float*)d_in[7];
    const float* bv = (const float*)d_in[8];
    const float* wo = (const float*)d_in[9];
    const float* bo = (const float*)d_in[10];

    float* out  = (float*)d_out;
    float* attn = out + OUT_ELEMS;

    float *qh, *kh, *vh, *ctx;
    __nv_bfloat16 *xcat, *wcat, *qcat, *kcat;
    cudaGetSymbolAddress((void**)&qh, g_qh);
    cudaGetSymbolAddress((void**)&kh, g_kh);
    cudaGetSymbolAddress((void**)&vh, g_vh);
    cudaGetSymbolAddress((void**)&ctx, g_ctx);
    cudaGetSymbolAddress((void**)&xcat, g_xcat);
    cudaGetSymbolAddress((void**)&wcat, g_wcat);
    cudaGetSymbolAddress((void**)&qcat, g_qcat);
    cudaGetSymbolAddress((void**)&kcat, g_kcat);

    cudaFuncSetAttribute(gemm_mma_kernel, cudaFuncAttributeMaxDynamicSharedMemorySize, GEMM_SMEM_SZ);
    cudaFuncSetAttribute(ctx128_kernel, cudaFuncAttributeMaxDynamicSharedMemorySize, 49152);

    const dim3 gProj(8, 32, 1);       // N/128, M/128
    const dim3 gScore(16, 16, 32);    // S/128, S/128, B*H
    const dim3 gTr(32, 32);
    const int nSplitX = M_ * (D_ / 2) / 256;        // 8192 blocks
    const int nSplitH = (B_ * H_ * S_) * (DK_ / 2) / 256; // 8192 blocks

    // Q projection
    transpose_split_cat_kernel<<<gTr, 256>>>(wq, wcat);
    split_cat_kernel<1024, 0><<<nSplitX, 256>>>(q, xcat);
    gemm_mma_kernel<<<gProj, 256, GEMM_SMEM_SZ>>>(xcat, 3 * D_, 0, wcat, 3 * D_, 0,
                                                  qh, D_, 0, bq, 1.0f, 3 * D_, 1);
    // K projection
    transpose_split_cat_kernel<<<gTr, 256>>>(wk, wcat);
    split_cat_kernel<1024, 0><<<nSplitX, 256>>>(k, xcat);
    gemm_mma_kernel<<<gProj, 256, GEMM_SMEM_SZ>>>(xcat, 3 * D_, 0, wcat, 3 * D_, 0,
                                                  kh, D_, 0, bk, 1.0f, 3 * D_, 1);
    // V projection
    transpose_split_cat_kernel<<<gTr, 256>>>(wv, wcat);
    split_cat_kernel<1024, 0><<<nSplitX, 256>>>(v, xcat);
    gemm_mma_kernel<<<gProj, 256, GEMM_SMEM_SZ>>>(xcat, 3 * D_, 0, wcat, 3 * D_, 0,
                                                  vh, D_, 0, bv, 1.0f, 3 * D_, 1);

    // Head splits for scores (A-style for Q, B-style for K)
    split_cat_kernel<64, 0><<<nSplitH, 256>>>(qh, qcat);
    split_cat_kernel<64, 1><<<nSplitH, 256>>>(kh, kcat);

    // Scores: per-head GEMM [2048 x 2048], K'=192, scale 1/8, into attn
    gemm_mma_kernel<<<gScore, 256, GEMM_SMEM_SZ>>>(
        qcat, 3 * DK_, (long long)S_ * 3 * DK_,
        kcat, 3 * DK_, (long long)S_ * 3 * DK_,
        attn, S_, (long long)S_ * S_,
        nullptr, 0.125f, 3 * DK_, 0);

    softmax_kernel<<<B_ * H_ * S_, 256>>>(attn);
    ctx128_kernel<<<dim3(S_ / 128, B_ * H_), 128, 49152>>>(attn, vh, ctx);

    // Output projection
    transpose_split_cat_kernel<<<gTr, 256>>>(wo, wcat);
    split_cat_kernel<1024, 0><<<nSplitX, 256>>>(ctx, xcat);
    gemm_mma_kernel<<<gProj, 256, GEMM_SMEM_SZ>>>(xcat, 3 * D_, 0, wcat, 3 * D_, 0,
                                                  out, D_, 0, bo, 1.0f, 3 * D_, 0);
}

// round 4
// speedup vs baseline: 2.2631x; 1.4844x over previous
#include <cuda_runtime.h>
#include <cuda_bf16.h>
#include <cstdint>
#include <math.h>

#define B_  2
#define S_  2048
#define D_  1024
#define H_  16
#define DK_ 64
#define M_  (B_ * S_)
#define OUT_ELEMS (B_ * S_ * D_)

// ---------------------------------------------------------------------------
__device__ __forceinline__ uint32_t smem_u32(const void* p) {
    uint32_t a;
    asm("{ .reg .u64 t; cvta.to.shared.u64 t, %1; cvt.u32.u64 %0, t; }" : "=r"(a) : "l"(p));
    return a;
}
#define SWZ128(off) ((off) ^ (((off) >> 3) & 0x70))

__device__ __forceinline__ void cp_async16(uint32_t dst, const void* src) {
    asm volatile("cp.async.cg.shared.global [%0], [%1], 16;" :: "r"(dst), "l"(src));
}
#define CP_COMMIT() asm volatile("cp.async.commit_group;" ::: "memory")
#define CP_WAIT(n)  asm volatile("cp.async.wait_group %0;" :: "n"(n) : "memory")

__device__ __forceinline__ void ldsm4(uint32_t* r, uint32_t addr) {
    asm volatile("ldmatrix.sync.aligned.m8n8.x4.shared.b16 {%0,%1,%2,%3}, [%4];"
                 : "=r"(r[0]), "=r"(r[1]), "=r"(r[2]), "=r"(r[3]) : "r"(addr));
}

__device__ __forceinline__ void mma_bf16(float* c, const uint32_t* a, uint32_t b0, uint32_t b1) {
    asm volatile(
        "mma.sync.aligned.m16n8k16.row.col.f32.bf16.bf16.f32 "
        "{%0,%1,%2,%3}, {%4,%5,%6,%7}, {%8,%9}, {%0,%1,%2,%3};"
        : "+f"(c[0]), "+f"(c[1]), "+f"(c[2]), "+f"(c[3])
        : "r"(a[0]), "r"(a[1]), "r"(a[2]), "r"(a[3]), "r"(b0), "r"(b1));
}

// ---------------------------------------------------------------------------
// Scratch
// ---------------------------------------------------------------------------
__device__ float g_qh[B_ * H_ * S_ * DK_];
__device__ float g_kh[B_ * H_ * S_ * DK_];
__device__ float g_vh[B_ * H_ * S_ * DK_];
__device__ __nv_bfloat16 g_xcat3[3 * M_ * 3 * D_];       // 3 batched A' [4096,3072]
__device__ __nv_bfloat16 g_wcat3[3 * D_ * 3 * D_];       // 3 batched B' [1024,3072]
__device__ __nv_bfloat16 g_qcat[B_ * H_ * S_ * 3 * DK_];
__device__ __nv_bfloat16 g_kcat[B_ * H_ * S_ * 3 * DK_];
__device__ __nv_bfloat16 g_vth[B_ * H_ * DK_ * S_];      // V^T hi [bh][d][t]
__device__ __nv_bfloat16 g_vtl[B_ * H_ * DK_ * S_];      // V^T lo
__device__ float g_bias3[3 * D_];

// ---------------------------------------------------------------------------
// Split fp32 -> bf16 concat. STYLE 0: [hi|lo|hi]. STYLE 1: [hi|hi|lo].
// ---------------------------------------------------------------------------
template<int KIN, int STYLE>
__global__ __launch_bounds__(256) void split_cat_kernel(
    const float* __restrict__ x, __nv_bfloat16* __restrict__ out)
{
    const int i2 = blockIdx.x * 256 + threadIdx.x;
    const int r  = i2 / (KIN / 2);
    const int kp = (i2 - r * (KIN / 2)) * 2;
    float2 f = *(const float2*)(x + (size_t)r * KIN + kp);
    __nv_bfloat16 h0 = __float2bfloat16(f.x);
    __nv_bfloat16 h1 = __float2bfloat16(f.y);
    __nv_bfloat16 l0 = __float2bfloat16(f.x - __bfloat162float(h0));
    __nv_bfloat16 l1 = __float2bfloat16(f.y - __bfloat162float(h1));
    __nv_bfloat162 hv; hv.x = h0; hv.y = h1;
    __nv_bfloat162 lv; lv.x = l0; lv.y = l1;
    __nv_bfloat16* base = out + (size_t)r * 3 * KIN;
    *(__nv_bfloat162*)(base + kp) = hv;
    if (STYLE == 0) {
        *(__nv_bfloat162*)(base + KIN + kp)     = lv;
        *(__nv_bfloat162*)(base + 2 * KIN + kp) = hv;
    } else {
        *(__nv_bfloat162*)(base + KIN + kp)     = hv;
        *(__nv_bfloat162*)(base + 2 * KIN + kp) = lv;
    }
}

// Transpose [1024,1024] fp32 -> [1024, 3072] bf16 = [Bh | Bh | Bl]
__global__ __launch_bounds__(256) void transpose_split_cat_kernel(
    const float* __restrict__ w, __nv_bfloat16* __restrict__ out)
{
    __shared__ float tile[32][33];
    const int k0 = blockIdx.y * 32;
    const int n0 = blockIdx.x * 32;
    const int tx = threadIdx.x & 31;
    const int ty = threadIdx.x >> 5;
#pragma unroll
    for (int i = 0; i < 4; i++)
        tile[ty + i * 8][tx] = w[(size_t)(k0 + ty + i * 8) * D_ + n0 + tx];
    __syncthreads();
#pragma unroll
    for (int i = 0; i < 4; i++) {
        float f = tile[tx][ty + i * 8];
        __nv_bfloat16 h = __float2bfloat16(f);
        __nv_bfloat16 l = __float2bfloat16(f - __bfloat162float(h));
        const size_t n = n0 + ty + i * 8;
        const size_t k = k0 + tx;
        out[n * 3072 + k]        = h;
        out[n * 3072 + 1024 + k] = h;
        out[n * 3072 + 2048 + k] = l;
    }
}

// V^T hi/lo: vh [bh][t][64] fp32 -> vth/vtl [bh][64][t] bf16
__global__ __launch_bounds__(256) void vtrans_kernel(
    const float* __restrict__ vh, __nv_bfloat16* __restrict__ th, __nv_bfloat16* __restrict__ tl)
{
    __shared__ float tile[32][33];
    const int z = blockIdx.z;
    const int t0 = blockIdx.x * 32;
    const int d0 = blockIdx.y * 32;
    const int tx = threadIdx.x & 31;
    const int ty = threadIdx.x >> 5;
#pragma unroll
    for (int i = 0; i < 4; i++)
        tile[ty + i * 8][tx] = vh[((size_t)z * S_ + t0 + ty + i * 8) * DK_ + d0 + tx];
    __syncthreads();
#pragma unroll
    for (int i = 0; i < 4; i++) {
        float f = tile[tx][ty + i * 8];
        __nv_bfloat16 h = __float2bfloat16(f);
        __nv_bfloat16 l = __float2bfloat16(f - __bfloat162float(h));
        const size_t o = ((size_t)z * DK_ + d0 + ty + i * 8) * S_ + t0 + tx;
        th[o] = h;
        tl[o] = l;
    }
}

__global__ void bias3_kernel(const float* bq, const float* bk, const float* bv, float* out)
{
    const int i = blockIdx.x * 256 + threadIdx.x;
    if (i < 1024) out[i] = bq[i];
    else if (i < 2048) out[i] = bk[i - 1024];
    else out[i] = bv[i - 2048];
}

// ---------------------------------------------------------------------------
// bf16 mma GEMM. Block 128x128, 8 warps 64x32, BK=64, 3-stage cp.async.
// mode 0: plain C[m*ldc+col]*scale (+bias[col]).
// mode 1: z selects dst (C,C1,C2) + head-split layout; bias offset z*1024.
// ---------------------------------------------------------------------------
#define GEMM_STAGES 3
#define GEMM_SMEM_SZ (GEMM_STAGES * 32768)

__global__ __launch_bounds__(256) void gemm_mma_kernel(
    const __nv_bfloat16* __restrict__ A, int lda, long long strideA,
    const __nv_bfloat16* __restrict__ B, int ldb, long long strideB,
    float* __restrict__ C, int ldc, long long strideC,
    const float* __restrict__ bias, float scale, int Kp, int mode,
    float* __restrict__ C1, float* __restrict__ C2)
{
    extern __shared__ char smem[];
    const uint32_t sbase = smem_u32(smem);
    const int t = threadIdx.x;
    const int lane = t & 31;
    const int wid = t >> 5;
    const int wm = (wid >> 2) * 64;
    const int wn = (wid & 3) * 32;
    const int m0 = blockIdx.y * 128;
    const int n0 = blockIdx.x * 128;
    const int z = blockIdx.z;

    const char* Ab = (const char*)(A + (size_t)z * strideA + (size_t)m0 * lda);
    const char* Bb = (const char*)(B + (size_t)z * strideB + (size_t)n0 * ldb);

    const int ktiles = Kp >> 6;

    auto load_stage = [&](int kt, int s) {
        const uint32_t sa = sbase + (uint32_t)s * 32768u;
#pragma unroll
        for (int i = 0; i < 4; i++) {
            const int id = t + i * 256;
            const int row = id >> 3;
            const int cb = (id & 7) << 4;
            const uint32_t sw = SWZ128((uint32_t)(row * 128 + cb));
            const size_t goff = (size_t)row * lda * 2 + (size_t)kt * 128 + cb;
            const size_t goffB = (size_t)row * ldb * 2 + (size_t)kt * 128 + cb;
            cp_async16(sa + sw, Ab + goff);
            cp_async16(sa + 16384u + sw, Bb + goffB);
        }
        CP_COMMIT();
    };

    float acc[4][4][4];
#pragma unroll
    for (int i = 0; i < 4; i++)
#pragma unroll
        for (int j = 0; j < 4; j++)
#pragma unroll
            for (int k = 0; k < 4; k++) acc[i][j][k] = 0.f;

    load_stage(0, 0);
    if (ktiles > 1) load_stage(1, 1);

    int st = 0;
    for (int kt = 0; kt < ktiles; kt++) {
        if (kt + 2 < ktiles) {
            int s2 = st + 2; if (s2 >= GEMM_STAGES) s2 -= GEMM_STAGES;
            load_stage(kt + 2, s2);
            CP_WAIT(2);
        } else {
            CP_WAIT(0);
        }
        __syncthreads();

        const uint32_t sa = sbase + (uint32_t)st * 32768u;
        const uint32_t sb = sa + 16384u;

#pragma unroll
        for (int ks = 0; ks < 4; ks++) {
            uint32_t af[4][4];
#pragma unroll
            for (int im = 0; im < 4; im++) {
                const int row = wm + im * 16 + (lane & 15);
                const int byt = ks * 32 + ((lane >> 4) << 4);
                ldsm4(af[im], sa + SWZ128((uint32_t)(row * 128 + byt)));
            }
            uint32_t bf[2][4];
#pragma unroll
            for (int j = 0; j < 2; j++) {
                const int nrow = wn + j * 16 + (lane & 7) + ((lane & 16) ? 8 : 0);
                const int byt = ks * 32 + ((lane & 8) ? 16 : 0);
                ldsm4(bf[j], sb + SWZ128((uint32_t)(nrow * 128 + byt)));
            }
#pragma unroll
            for (int im = 0; im < 4; im++)
#pragma unroll
                for (int in = 0; in < 4; in++) {
                    const uint32_t* bb = &bf[in >> 1][(in & 1) * 2];
                    mma_bf16(acc[im][in], af[im], bb[0], bb[1]);
                }
        }
        __syncthreads();
        st++; if (st >= GEMM_STAGES) st = 0;
    }

    float* dst0 = (mode == 1) ? (z == 0 ? C : (z == 1 ? C1 : C2)) : (C + (size_t)z * strideC);
    const float* bp = (mode == 1) ? (bias + z * 1024) : bias;

#pragma unroll
    for (int im = 0; im < 4; im++) {
        const int r0 = m0 + wm + im * 16 + (lane >> 2);
#pragma unroll
        for (int in = 0; in < 4; in++) {
            const int col = n0 + wn + in * 8 + (lane & 3) * 2;
            float2 v0, v1;
            v0.x = acc[im][in][0] * scale;
            v0.y = acc[im][in][1] * scale;
            v1.x = acc[im][in][2] * scale;
            v1.y = acc[im][in][3] * scale;
            if (bp) {
                const float b0 = __ldg(bp + col), b1 = __ldg(bp + col + 1);
                v0.x += b0; v0.y += b1;
                v1.x += b0; v1.y += b1;
            }
            if (mode == 1) {
                const int h = col >> 6, d0 = col & 63;
                const int bb0 = r0 >> 11, s0 = r0 & (S_ - 1);
                const int r1 = r0 + 8;
                const int bb1 = r1 >> 11, s1 = r1 & (S_ - 1);
                *(float2*)(dst0 + (((size_t)(bb0 * H_ + h) * S_ + s0) * DK_ + d0)) = v0;
                *(float2*)(dst0 + (((size_t)(bb1 * H_ + h) * S_ + s1) * DK_ + d0)) = v1;
            } else {
                *(float2*)(dst0 + (size_t)r0 * ldc + col) = v0;
                *(float2*)(dst0 + (size_t)(r0 + 8) * ldc + col) = v1;
            }
        }
    }
}

// ---------------------------------------------------------------------------
// Row softmax in-place
// ---------------------------------------------------------------------------
__global__ __launch_bounds__(256) void softmax_kernel(float* __restrict__ attn)
{
    const size_t row = blockIdx.x;
    float* p = attn + row * S_;
    const int t = threadIdx.x;

    float v[8];
    float mx = -1e30f;
#pragma unroll
    for (int i = 0; i < 8; i++) { v[i] = p[t + 256 * i]; mx = fmaxf(mx, v[i]); }
#pragma unroll
    for (int o = 16; o; o >>= 1) mx = fmaxf(mx, __shfl_xor_sync(0xffffffffu, mx, o));

    __shared__ float red[8];
    if ((t & 31) == 0) red[t >> 5] = mx;
    __syncthreads();
    mx = red[0];
#pragma unroll
    for (int i = 1; i < 8; i++) mx = fmaxf(mx, red[i]);
    __syncthreads();

    float sum = 0.f;
#pragma unroll
    for (int i = 0; i < 8; i++) { v[i] = expf(v[i] - mx); sum += v[i]; }
#pragma unroll
    for (int o = 16; o; o >>= 1) sum += __shfl_xor_sync(0xffffffffu, sum, o);
    if ((t & 31) == 0) red[t >> 5] = sum;
    __syncthreads();
    sum = 0.f;
#pragma unroll
    for (int i = 0; i < 8; i++) sum += red[i];

    const float inv = 1.0f / sum;
#pragma unroll
    for (int i = 0; i < 8; i++) p[t + 256 * i] = v[i] * inv;
}

// ---------------------------------------------------------------------------
// ctx via mma: per head, C[128 tile][64] = attn @ V, 3-product hi/lo.
// attn fp32 converted in-kernel; V^T hi/lo bf16 via cp.async.
// Epilogue writes xcat [hi|lo|hi] directly (feeds out-projection).
// 8 warps (4x2, warp 32x32), BK=64, 2-stage.
// ---------------------------------------------------------------------------
#define CTX_STAGE 49152
#define CTX_SMEM (2 * CTX_STAGE)

__global__ __launch_bounds__(256) void ctx_mma_kernel(
    const float* __restrict__ attn, const __nv_bfloat16* __restrict__ vth,
    const __nv_bfloat16* __restrict__ vtl, __nv_bfloat16* __restrict__ xcat)
{
    extern __shared__ char smem[];
    const uint32_t sbase = smem_u32(smem);
    const int t = threadIdx.x, lane = t & 31, wid = t >> 5;
    const int wm = (wid >> 1) * 32, wn = (wid & 1) * 32;
    const int z = blockIdx.z, m0 = blockIdx.x * 128;

    const float* Ab = attn + ((size_t)z * S_ + m0) * S_;
    const char* Vh = (const char*)(vth + (size_t)z * DK_ * S_);
    const char* Vl = (const char*)(vtl + (size_t)z * DK_ * S_);

    const int arow = t >> 1, ach = (t & 1) * 32;

    float4 a4[8];

    float acc[2][4][4];
#pragma unroll
    for (int i = 0; i < 2; i++)
#pragma unroll
        for (int j = 0; j < 4; j++)
#pragma unroll
            for (int k = 0; k < 4; k++) acc[i][j][k] = 0.f;

    // prologue: A regs chunk 0, V cp.async chunk 0 -> stage 0
    {
        const float* p = Ab + (size_t)arow * S_ + ach;
#pragma unroll
        for (int j = 0; j < 8; j++) a4[j] = *(const float4*)(p + j * 4);
    }
    {
        const uint32_t vb = sbase + 32768u;
#pragma unroll
        for (int i = 0; i < 2; i++) {
            const int id = t + i * 256;
            const int row = id >> 3, cb = (id & 7) << 4;
            const uint32_t sw = SWZ128((uint32_t)(row * 128 + cb));
            const size_t g = ((size_t)row * S_) * 2 + cb;
            cp_async16(vb + sw, Vh + g);
            cp_async16(vb + 8192u + sw, Vl + g);
        }
        CP_COMMIT();
    }

    for (int c = 0; c < 32; c++) {
        const int s = c & 1;
        // store A regs (chunk c) -> stage s as bf16 hi/lo
        {
            char* base = smem + s * CTX_STAGE;
#pragma unroll
            for (int j = 0; j < 4; j++) {
                float f[8] = {a4[2*j].x, a4[2*j].y, a4[2*j].z, a4[2*j].w,
                              a4[2*j+1].x, a4[2*j+1].y, a4[2*j+1].z, a4[2*j+1].w};
                __nv_bfloat16 hi[8], lo[8];
#pragma unroll
                for (int e = 0; e < 8; e++) {
                    hi[e] = __float2bfloat16(f[e]);
                    lo[e] = __float2bfloat16(f[e] - __bfloat162float(hi[e]));
                }
                const uint32_t off = SWZ128((uint32_t)(arow * 128 + ach * 2 + j * 16));
                *(uint4*)(base + off)         = *(uint4*)hi;
                *(uint4*)(base + 16384 + off) = *(uint4*)lo;
            }
        }
        // prefetch A regs for chunk c+1
        if (c < 31) {
            const float* p = Ab + (size_t)arow * S_ + (c + 1) * 64 + ach;
#pragma unroll
            for (int j = 0; j < 8; j++) a4[j] = *(const float4*)(p + j * 4);
        }
        CP_WAIT(0);
        __syncthreads();
        // prefetch V chunk c+1 -> stage s^1 (safe: everyone done with mma(c-1))
        if (c < 31) {
            const uint32_t vb = sbase + (uint32_t)(s ^ 1) * CTX_STAGE + 32768u;
#pragma unroll
            for (int i = 0; i < 2; i++) {
                const int id = t + i * 256;
                const int row = id >> 3, cb = (id & 7) << 4;
                const uint32_t sw = SWZ128((uint32_t)(row * 128 + cb));
                const size_t g = ((size_t)row * S_ + (size_t)(c + 1) * 64) * 2 + cb;
                cp_async16(vb + sw, Vh + g);
                cp_async16(vb + 8192u + sw, Vl + g);
            }
            CP_COMMIT();
        }

        const uint32_t sa = sbase + (uint32_t)s * CTX_STAGE;
#pragma unroll
        for (int ks = 0; ks < 4; ks++) {
            uint32_t ah[2][4], al[2][4];
#pragma unroll
            for (int im = 0; im < 2; im++) {
                const int row = wm + im * 16 + (lane & 15);
                const int byt = ks * 32 + ((lane >> 4) << 4);
                const uint32_t o = SWZ128((uint32_t)(row * 128 + byt));
                ldsm4(ah[im], sa + o);
                ldsm4(al[im], sa + 16384u + o);
            }
            uint32_t vhf[2][4], vlf[2][4];
#pragma unroll
            for (int j = 0; j < 2; j++) {
                const int nrow = wn + j * 16 + (lane & 7) + ((lane & 16) ? 8 : 0);
                const int byt = ks * 32 + ((lane & 8) ? 16 : 0);
                const uint32_t o = SWZ128((uint32_t)(nrow * 128 + byt));
                ldsm4(vhf[j], sa + 32768u + o);
                ldsm4(vlf[j], sa + 40960u + o);
            }
#pragma unroll
            for (int im = 0; im < 2; im++)
#pragma unroll
                for (int in = 0; in < 4; in++) {
                    const uint32_t* bh = &vhf[in >> 1][(in & 1) * 2];
                    const uint32_t* bl = &vlf[in >> 1][(in & 1) * 2];
                    mma_bf16(acc[im][in], ah[im], bh[0], bh[1]);
                    mma_bf16(acc[im][in], ah[im], bl[0], bl[1]);
                    mma_bf16(acc[im][in], al[im], bh[0], bh[1]);
                }
        }
    }

    // epilogue: write xcat [hi|lo|hi]
    const int bb = z >> 4, h = z & 15;
#pragma unroll
    for (int im = 0; im < 2; im++) {
        const int r0 = m0 + wm + im * 16 + (lane >> 2);
#pragma unroll
        for (int in = 0; in < 4; in++) {
            const int col = wn + in * 8 + (lane & 3) * 2;
            const size_t xcol = (size_t)h * 64 + col;
#pragma unroll
            for (int half = 0; half < 2; half++) {
                const int r = r0 + half * 8;
                const float f0 = acc[im][in][half * 2 + 0];
                const float f1 = acc[im][in][half * 2 + 1];
                __nv_bfloat162 h2, l2;
                h2.x = __float2bfloat16(f0);
                h2.y = __float2bfloat16(f1);
                l2.x = __float2bfloat16(f0 - __bfloat162float(h2.x));
                l2.y = __float2bfloat16(f1 - __bfloat162float(h2.y));
                __nv_bfloat16* row = xcat + ((size_t)bb * S_ + r) * 3072;
                *(__nv_bfloat162*)(row + xcol)        = h2;
                *(__nv_bfloat162*)(row + 1024 + xcol) = l2;
                *(__nv_bfloat162*)(row + 2048 + xcol) = h2;
            }
        }
    }
}

// ---------------------------------------------------------------------------
extern "C" void kernel_launch(void* const* d_in, const int* in_sizes, int n_in,
                              void* d_out, int out_size)
{
    const float* q  = (const float*)d_in[0];
    const float* k  = (const float*)d_in[1];
    const float* v  = (const float*)d_in[2];
    const float* wq = (const float*)d_in[3];
    const float* bq = (const float*)d_in[4];
    const float* wk = (const float*)d_in[5];
    const float* bk = (const float*)d_in[6];
    const float* wv = (const float*)d_in[7];
    const float* bv = (const float*)d_in[8];
    const float* wo = (const float*)d_in[9];
    const float* bo = (const float*)d_in[10];

    float* out  = (float*)d_out;
    float* attn = out + OUT_ELEMS;

    float *qh, *kh, *vh, *bias3;
    __nv_bfloat16 *xcat3, *wcat3, *qcat, *kcat, *vth, *vtl;
    cudaGetSymbolAddress((void**)&qh, g_qh);
    cudaGetSymbolAddress((void**)&kh, g_kh);
    cudaGetSymbolAddress((void**)&vh, g_vh);
    cudaGetSymbolAddress((void**)&xcat3, g_xcat3);
    cudaGetSymbolAddress((void**)&wcat3, g_wcat3);
    cudaGetSymbolAddress((void**)&qcat, g_qcat);
    cudaGetSymbolAddress((void**)&kcat, g_kcat);
    cudaGetSymbolAddress((void**)&vth, g_vth);
    cudaGetSymbolAddress((void**)&vtl, g_vtl);
    cudaGetSymbolAddress((void**)&bias3, g_bias3);

    cudaFuncSetAttribute(gemm_mma_kernel, cudaFuncAttributeMaxDynamicSharedMemorySize, GEMM_SMEM_SZ);
    cudaFuncSetAttribute(ctx_mma_kernel, cudaFuncAttributeMaxDynamicSharedMemorySize, CTX_SMEM);

    const dim3 gTr(32, 32);
    const int nSplitX = M_ * (D_ / 2) / 256;
    const int nSplitH = (B_ * H_ * S_) * (DK_ / 2) / 256;
    const long long secX = (long long)M_ * 3 * D_;
    const long long secW = (long long)D_ * 3 * D_;

    // Weight transposes + activation splits + bias concat
    transpose_split_cat_kernel<<<gTr, 256>>>(wq, wcat3);
    transpose_split_cat_kernel<<<gTr, 256>>>(wk, wcat3 + secW);
    transpose_split_cat_kernel<<<gTr, 256>>>(wv, wcat3 + 2 * secW);
    split_cat_kernel<1024, 0><<<nSplitX, 256>>>(q, xcat3);
    split_cat_kernel<1024, 0><<<nSplitX, 256>>>(k, xcat3 + secX);
    split_cat_kernel<1024, 0><<<nSplitX, 256>>>(v, xcat3 + 2 * secX);
    bias3_kernel<<<12, 256>>>(bq, bk, bv, bias3);

    // Batched QKV projection (z=3)
    gemm_mma_kernel<<<dim3(8, 32, 3), 256, GEMM_SMEM_SZ>>>(
        xcat3, 3 * D_, secX, wcat3, 3 * D_, secW,
        qh, D_, 0, bias3, 1.0f, 3 * D_, 1, kh, vh);

    // wo transpose (after QKV GEMM has consumed wcat3 section 0)
    transpose_split_cat_kernel<<<gTr, 256>>>(wo, wcat3);

    // V^T hi/lo, Q/K splits
    vtrans_kernel<<<dim3(S_ / 32, DK_ / 32, B_ * H_), 256>>>(vh, vth, vtl);
    split_cat_kernel<64, 0><<<nSplitH, 256>>>(qh, qcat);
    split_cat_kernel<64, 1><<<nSplitH, 256>>>(kh, kcat);

    // Scores
    gemm_mma_kernel<<<dim3(16, 16, 32), 256, GEMM_SMEM_SZ>>>(
        qcat, 3 * DK_, (long long)S_ * 3 * DK_,
        kcat, 3 * DK_, (long long)S_ * 3 * DK_,
        attn, S_, (long long)S_ * S_,
        nullptr, 0.125f, 3 * DK_, 0, nullptr, nullptr);

    softmax_kernel<<<B_ * H_ * S_, 256>>>(attn);

    // ctx (writes xcat3 section 0 directly)
    ctx_mma_kernel<<<dim3(16, 1, 32), 256, CTX_SMEM>>>(attn, vth, vtl, xcat3);

    // Output projection
    gemm_mma_kernel<<<dim3(8, 32, 1), 256, GEMM_SMEM_SZ>>>(
        xcat3, 3 * D_, 0, wcat3, 3 * D_, 0,
        out, D_, 0, bo, 1.0f, 3 * D_, 0, nullptr, nullptr);
}